// round 6
// baseline (speedup 1.0000x reference)
#include <cuda_runtime.h>
#include <cuda_fp16.h>

#define NN 100000
#define EE 1250000
#define HH 64
#define BN_EPS 1e-5f
#define SCAN_BLOCKS 98   // ceil(NN / 1024)

// ---------------- scratch (static device arrays; no allocation) ----------------
__device__ float   g_h0[NN * HH];     // post-fc activation (residual source)
__device__ float   g_h1[NN * HH];     // layer-0 output
__device__ __half2 g_hw16[NN * 32];   // transformed features (fp16), pre-scaled by dis[row]
__device__ float   g_dis[NN];         // deg^-1/2 (deg includes self loop)
__device__ int     g_cnt[NN];
__device__ int     g_off[NN + 1];
__device__ int     g_cur[NN];
__device__ int     g_csr[EE];
__device__ int     g_blkflag[128];
__device__ int     g_blkagg[128];
__device__ int     g_blkpref[128];

// ---------------- f32x2 helpers ----------------
typedef unsigned long long ull;
__device__ __forceinline__ void ffma2(ull& d, ull a, ull b) {
    asm("fma.rn.f32x2 %0, %1, %2, %0;" : "+l"(d) : "l"(a), "l"(b));
}
__device__ __forceinline__ float lo32(ull v) {
    return __uint_as_float((unsigned)(v & 0xFFFFFFFFull));
}
__device__ __forceinline__ float hi32(ull v) {
    return __uint_as_float((unsigned)(v >> 32));
}

// ---------------- CSR build ----------------
__global__ void zero_k() {
    int i = blockIdx.x * blockDim.x + threadIdx.x;
    if (i < NN) g_cnt[i] = 0;
    if (i < 128) g_blkflag[i] = 0;
}

__global__ void hist_k(const int* __restrict__ dst) {
    int i = blockIdx.x * blockDim.x + threadIdx.x;
    if (i < EE) atomicAdd(&g_cnt[dst[i]], 1);
}

// single-kernel decoupled-lookback scan + dis/cur init
__global__ __launch_bounds__(1024)
void scanfuse_k() {
    __shared__ int sh[1024];
    __shared__ int s_pref;
    int b = blockIdx.x, tid = threadIdx.x;
    int i = b * 1024 + tid;
    int v = (i < NN) ? g_cnt[i] : 0;
    sh[tid] = v;
    __syncthreads();
    #pragma unroll
    for (int d = 1; d < 1024; d <<= 1) {
        int t = (tid >= d) ? sh[tid - d] : 0;
        __syncthreads();
        sh[tid] += t;
        __syncthreads();
    }
    int total = sh[1023];

    if (tid == 0) {
        g_blkagg[b] = total;
        __threadfence();
        atomicExch(&g_blkflag[b], 1);
        int pref = 0;
        for (int p = b - 1; p >= 0; ) {
            int f = atomicAdd(&g_blkflag[p], 0);
            if (f == 2)      { pref += atomicAdd(&g_blkpref[p], 0); break; }
            else if (f == 1) { pref += atomicAdd(&g_blkagg[p], 0);  p--;   }
        }
        g_blkpref[b] = pref + total;
        __threadfence();
        atomicExch(&g_blkflag[b], 2);
        s_pref = pref;
    }
    __syncthreads();
    int pref = s_pref;

    if (i < NN) {
        g_off[i] = pref + sh[tid] - v;
        g_dis[i] = rsqrtf((float)(v + 1));
        g_cur[i] = 0;
    }
    if (b == SCAN_BLOCKS - 1 && tid == 0) g_off[NN] = EE;
}

__global__ void fill_k(const int* __restrict__ src, const int* __restrict__ dst) {
    int i = blockIdx.x * blockDim.x + threadIdx.x;
    if (i < EE) {
        int d = dst[i];
        int p = g_off[d] + atomicAdd(&g_cur[d], 1);
        g_csr[p] = src[i];
    }
}

// ---------------- GEMM: out = A[row, K] @ W[K, 64] (+ epilogue), f32x2 ----------------
// Thread tile: 4 rows (r0..r0+3) x 4 cols {2tx, 2tx+1, 2tx+32, 2tx+33}.
// acc packs column pairs. a-operand: duplicated-pair from transposed smem (LDS.64,
// broadcast). b-operand: natural pair from ws (LDS.64, conflict-free). No pack MOVs.
// MODE 0: fc epilogue -> relu(bn0(acc + fc_b)) to float
// MODE 1: conv epilogue -> half2( acc * dis[row] )
#define WS_STRIDE 68
#define XD_STRIDE 130

template <int KDIM, int MODE>
__global__ __launch_bounds__(256)
void gemm_k(const float* __restrict__ A, const float* __restrict__ W,
            void* __restrict__ outv,
            const float* __restrict__ fcb, const float* __restrict__ bng,
            const float* __restrict__ bnb, const float* __restrict__ bnm,
            const float* __restrict__ bnv)
{
    extern __shared__ float smem[];
    float* ws  = smem;                         // [64][WS_STRIDE]
    float* xsd = smem + 64 * WS_STRIDE;        // [64 k][XD_STRIDE] duplicated A^T

    int tid = threadIdx.x;
    int row0 = blockIdx.x * 64;
    int tx = tid & 15, ty = tid >> 4;
    int r0 = ty * 4;

    ull acc[4][2];                             // [row i][pair p]: p=0 cols(2tx,2tx+1), p=1 +32
    #pragma unroll
    for (int i = 0; i < 4; i++) { acc[i][0] = 0ull; acc[i][1] = 0ull; }

    #pragma unroll
    for (int kb = 0; kb < KDIM / 64; kb++) {
        // W chunk [64][64] -> ws stride 68 (float4 aligned)
        #pragma unroll
        for (int i = 0; i < 4; i++) {
            int idx = tid + i * 256;
            int kr = idx >> 4, c4 = idx & 15;
            float4 v = *(const float4*)&W[(kb * 64 + kr) * HH + c4 * 4];
            *(float4*)&ws[kr * WS_STRIDE + c4 * 4] = v;
        }
        // A tile [64 rows][64 cols] -> duplicated transposed xsd[k][(2r)^(2*(k>>2))]
        #pragma unroll
        for (int i = 0; i < 4; i++) {
            int idx = tid + i * 256;
            int r = idx >> 4, c4 = idx & 15;   // c4 = k>>2 for the 4 k's this thread stores
            int grow = row0 + r;
            float4 v = make_float4(0.f, 0.f, 0.f, 0.f);
            if (grow < NN)
                v = *(const float4*)&A[(long)grow * KDIM + kb * 64 + c4 * 4];
            int sw = (2 * r) ^ (2 * c4);
            *(float2*)&xsd[(c4 * 4 + 0) * XD_STRIDE + sw] = make_float2(v.x, v.x);
            *(float2*)&xsd[(c4 * 4 + 1) * XD_STRIDE + sw] = make_float2(v.y, v.y);
            *(float2*)&xsd[(c4 * 4 + 2) * XD_STRIDE + sw] = make_float2(v.z, v.z);
            *(float2*)&xsd[(c4 * 4 + 3) * XD_STRIDE + sw] = make_float2(v.w, v.w);
        }
        __syncthreads();

        #pragma unroll
        for (int k = 0; k < 64; k++) {
            const int sk = 2 * (k >> 2);       // compile-time after unroll
            ull b0 = *(const ull*)&ws[k * WS_STRIDE + 2 * tx];
            ull b1 = *(const ull*)&ws[k * WS_STRIDE + 2 * tx + 32];
            #pragma unroll
            for (int i = 0; i < 4; i++) {
                ull a = *(const ull*)&xsd[k * XD_STRIDE + ((2 * (r0 + i)) ^ sk)];
                ffma2(acc[i][0], a, b0);
                ffma2(acc[i][1], a, b1);
            }
        }
        __syncthreads();
    }

    if (MODE == 0) {
        float* out = (float*)outv;
        float2 G0 = *(const float2*)&bng[2 * tx],      G1 = *(const float2*)&bng[2 * tx + 32];
        float2 V0 = *(const float2*)&bnv[2 * tx],      V1 = *(const float2*)&bnv[2 * tx + 32];
        float2 M0 = *(const float2*)&bnm[2 * tx],      M1 = *(const float2*)&bnm[2 * tx + 32];
        float2 B0 = *(const float2*)&bnb[2 * tx],      B1 = *(const float2*)&bnb[2 * tx + 32];
        float2 F0 = *(const float2*)&fcb[2 * tx],      F1 = *(const float2*)&fcb[2 * tx + 32];
        float s0x = G0.x * rsqrtf(V0.x + BN_EPS), s0y = G0.y * rsqrtf(V0.y + BN_EPS);
        float s1x = G1.x * rsqrtf(V1.x + BN_EPS), s1y = G1.y * rsqrtf(V1.y + BN_EPS);
        #pragma unroll
        for (int i = 0; i < 4; i++) {
            int grow = row0 + r0 + i;
            if (grow < NN) {
                float2 o0, o1;
                o0.x = fmaxf((lo32(acc[i][0]) + F0.x - M0.x) * s0x + B0.x, 0.f);
                o0.y = fmaxf((hi32(acc[i][0]) + F0.y - M0.y) * s0y + B0.y, 0.f);
                o1.x = fmaxf((lo32(acc[i][1]) + F1.x - M1.x) * s1x + B1.x, 0.f);
                o1.y = fmaxf((hi32(acc[i][1]) + F1.y - M1.y) * s1y + B1.y, 0.f);
                *(float2*)&out[(long)grow * HH + 2 * tx]      = o0;
                *(float2*)&out[(long)grow * HH + 2 * tx + 32] = o1;
            }
        }
    } else {
        __half2* out = (__half2*)outv;         // row stride 32 half2
        #pragma unroll
        for (int i = 0; i < 4; i++) {
            int grow = row0 + r0 + i;
            if (grow < NN) {
                float dn = g_dis[grow];
                out[grow * 32 + tx]      = __floats2half2_rn(lo32(acc[i][0]) * dn,
                                                             hi32(acc[i][0]) * dn);
                out[grow * 32 + 16 + tx] = __floats2half2_rn(lo32(acc[i][1]) * dn,
                                                             hi32(acc[i][1]) * dn);
            }
        }
    }
}

// ---------------- aggregation: fp16 gather over CSR + bn + relu + residual ----------------
__global__ __launch_bounds__(256)
void agg_k(const __half2* __restrict__ hw,
           const float* __restrict__ cb, const float* __restrict__ bng,
           const float* __restrict__ bnb, const float* __restrict__ bnm,
           const float* __restrict__ bnv, const float* __restrict__ last,
           float* __restrict__ out)
{
    int gid = blockIdx.x * blockDim.x + threadIdx.x;
    int node = gid >> 4;
    if (node >= NN) return;
    int c4 = gid & 15;                       // owns halves [4*c4, 4*c4+4)

    const uint2* hwu = (const uint2*)hw;     // 16 uint2 per row
    uint2 rs = hwu[node * 16 + c4];          // self-loop term
    float2 f01 = __half22float2(*(const __half2*)&rs.x);
    float2 f23 = __half22float2(*(const __half2*)&rs.y);
    float4 acc = make_float4(f01.x, f01.y, f23.x, f23.y);
    float4 accB = make_float4(0.f, 0.f, 0.f, 0.f);

    int s = g_off[node], e = g_off[node + 1];
    int i = s;
    for (; i + 1 < e; i += 2) {
        int u0 = g_csr[i];
        int u1 = g_csr[i + 1];
        uint2 r0 = hwu[u0 * 16 + c4];
        uint2 r1 = hwu[u1 * 16 + c4];
        float2 a01 = __half22float2(*(const __half2*)&r0.x);
        float2 a23 = __half22float2(*(const __half2*)&r0.y);
        float2 b01 = __half22float2(*(const __half2*)&r1.x);
        float2 b23 = __half22float2(*(const __half2*)&r1.y);
        acc.x += a01.x; acc.y += a01.y; acc.z += a23.x; acc.w += a23.y;
        accB.x += b01.x; accB.y += b01.y; accB.z += b23.x; accB.w += b23.y;
    }
    if (i < e) {
        int u = g_csr[i];
        uint2 r0 = hwu[u * 16 + c4];
        float2 a01 = __half22float2(*(const __half2*)&r0.x);
        float2 a23 = __half22float2(*(const __half2*)&r0.y);
        acc.x += a01.x; acc.y += a01.y; acc.z += a23.x; acc.w += a23.y;
    }
    acc.x += accB.x; acc.y += accB.y; acc.z += accB.z; acc.w += accB.w;

    float dn = g_dis[node];
    int c = c4 * 4;
    float4 B  = *(const float4*)&cb[c];
    float4 G  = *(const float4*)&bng[c];
    float4 Be = *(const float4*)&bnb[c];
    float4 M  = *(const float4*)&bnm[c];
    float4 V  = *(const float4*)&bnv[c];
    float4 Ls = ((const float4*)last)[node * 16 + c4];

    float4 o;
    o.x = fmaxf((acc.x * dn + B.x - M.x) * (G.x * rsqrtf(V.x + BN_EPS)) + Be.x, 0.f) + Ls.x;
    o.y = fmaxf((acc.y * dn + B.y - M.y) * (G.y * rsqrtf(V.y + BN_EPS)) + Be.y, 0.f) + Ls.y;
    o.z = fmaxf((acc.z * dn + B.z - M.z) * (G.z * rsqrtf(V.z + BN_EPS)) + Be.z, 0.f) + Ls.z;
    o.w = fmaxf((acc.w * dn + B.w - M.w) * (G.w * rsqrtf(V.w + BN_EPS)) + Be.w, 0.f) + Ls.w;
    ((float4*)out)[node * 16 + c4] = o;
}

// ---------------- launch ----------------
extern "C" void kernel_launch(void* const* d_in, const int* in_sizes, int n_in,
                              void* d_out, int out_size)
{
    const float* x   = (const float*)d_in[0];
    const int*   ei  = (const int*)  d_in[1];
    const float* fcw = (const float*)d_in[2];
    const float* fcb = (const float*)d_in[3];
    const float* cw  = (const float*)d_in[4];
    const float* cb  = (const float*)d_in[5];
    const float* bng = (const float*)d_in[6];
    const float* bnb = (const float*)d_in[7];
    const float* bnm = (const float*)d_in[8];
    const float* bnv = (const float*)d_in[9];
    float* out = (float*)d_out;

    const int* src = ei;
    const int* dst = ei + EE;

    float *ph0, *ph1;
    __half2* phw;
    cudaGetSymbolAddress((void**)&ph0, g_h0);
    cudaGetSymbolAddress((void**)&ph1, g_h1);
    cudaGetSymbolAddress((void**)&phw, g_hw16);

    const int smem_bytes = (64 * WS_STRIDE + 64 * XD_STRIDE) * sizeof(float); // ~50.7KB
    cudaFuncSetAttribute(gemm_k<128, 0>, cudaFuncAttributeMaxDynamicSharedMemorySize, smem_bytes);
    cudaFuncSetAttribute(gemm_k<64, 1>,  cudaFuncAttributeMaxDynamicSharedMemorySize, smem_bytes);

    cudaStream_t s1;
    cudaEvent_t evFork, evJoin;
    cudaStreamCreateWithFlags(&s1, cudaStreamNonBlocking);
    cudaEventCreateWithFlags(&evFork, cudaEventDisableTiming);
    cudaEventCreateWithFlags(&evJoin, cudaEventDisableTiming);

    const int gblocks = (NN + 63) / 64;
    const int ablocks = (NN * 16 + 255) / 256;

    cudaEventRecord(evFork, 0);
    cudaStreamWaitEvent(s1, evFork, 0);

    // stream 0: CSR build
    zero_k <<<(NN + 255) / 256, 256>>>();
    hist_k <<<(EE + 255) / 256, 256>>>(dst);

    // stream s1: fc + conv0 transform (independent of CSR)
    gemm_k<128, 0><<<gblocks, 256, smem_bytes, s1>>>(x, fcw, ph0, fcb, bng, bnb, bnm, bnv);
    gemm_k<64, 1><<<gblocks, 256, smem_bytes, s1>>>(ph0, cw, phw,
                                                    nullptr, nullptr, nullptr, nullptr, nullptr);

    scanfuse_k<<<SCAN_BLOCKS, 1024>>>();
    fill_k <<<(EE + 255) / 256, 256>>>(src, dst);

    cudaEventRecord(evJoin, s1);
    cudaStreamWaitEvent(0, evJoin, 0);

    // layer 0 aggregation
    agg_k<<<ablocks, 256>>>(phw, cb, bng + 64, bnb + 64, bnm + 64, bnv + 64,
                            ph0, ph1);

    // layer 1
    gemm_k<64, 1><<<gblocks, 256, smem_bytes>>>(ph1, cw + HH * HH, phw,
                                                nullptr, nullptr, nullptr, nullptr, nullptr);
    agg_k<<<ablocks, 256>>>(phw, cb + HH, bng + 128, bnb + 128, bnm + 128, bnv + 128,
                            ph0, out);

    cudaEventDestroy(evFork);
    cudaEventDestroy(evJoin);
    cudaStreamDestroy(s1);
}